// round 8
// baseline (speedup 1.0000x reference)
#include <cuda_runtime.h>
#include <cuda_bf16.h>
#include <cstdint>

#define N_NODES 100000
#define N_FEATS 512
#define HIDDEN  64
#define N_CLS   40
#define N_EDGES 1600000
#define SCAN_B  1024
#define NBLK    ((N_NODES + SCAN_B - 1) / SCAN_B)   // 98

// ---------------- scratch ----------------
__device__ float g_dinv[N_NODES];
__device__ float g_h1[(size_t)N_NODES * HIDDEN];   // gemm1 out; reused as h2 [N][40]
__device__ float g_h2[(size_t)N_NODES * N_CLS];    // fused agg1+gemm2 output
__device__ float g_w2t[HIDDEN * N_CLS];            // [64][40]
__device__ __nv_bfloat16 g_w1hi[HIDDEN * N_FEATS];
__device__ __nv_bfloat16 g_w1lo[HIDDEN * N_FEATS];
__device__ int   g_deg[N_NODES];
__device__ int   g_rowptr[N_NODES];
__device__ int   g_cursor[N_NODES];
__device__ int   g_srcs[N_EDGES];
__device__ int   g_bsum[NBLK];

// ---------------- helpers ----------------
__device__ __forceinline__ uint32_t smem_u32(const void* p) {
    uint32_t a;
    asm("{ .reg .u64 t; cvta.to.shared.u64 t, %1; cvt.u32.u64 %0, t; }" : "=r"(a) : "l"(p));
    return a;
}
__device__ __forceinline__ void ldm_x4(uint32_t& r0, uint32_t& r1, uint32_t& r2,
                                       uint32_t& r3, uint32_t addr) {
    asm volatile("ldmatrix.sync.aligned.m8n8.x4.shared.b16 {%0,%1,%2,%3}, [%4];"
                 : "=r"(r0), "=r"(r1), "=r"(r2), "=r"(r3) : "r"(addr));
}
__device__ __forceinline__ void mma16816(float* d, const uint32_t* a,
                                         uint32_t b0, uint32_t b1) {
    asm volatile(
        "mma.sync.aligned.m16n8k16.row.col.f32.bf16.bf16.f32 "
        "{%0,%1,%2,%3}, {%4,%5,%6,%7}, {%8,%9}, {%0,%1,%2,%3};"
        : "+f"(d[0]), "+f"(d[1]), "+f"(d[2]), "+f"(d[3])
        : "r"(a[0]), "r"(a[1]), "r"(a[2]), "r"(a[3]), "r"(b0), "r"(b1));
}

// ---------------- fused prep ----------------
__global__ void k_prep(const float* __restrict__ W1, const float* __restrict__ W2) {
    int i = blockIdx.x * blockDim.x + threadIdx.x;
    if (i < HIDDEN * N_FEATS) {
        float v = W1[i];
        __nv_bfloat16 h = __float2bfloat16(v);
        g_w1hi[i] = h;
        g_w1lo[i] = __float2bfloat16(v - __bfloat162float(h));
    }
    if (i < HIDDEN * N_CLS) {
        int k = i / N_CLS, j = i - k * N_CLS;
        g_w2t[i] = W2[j * HIDDEN + k];
    }
    if (i < N_NODES) g_deg[i] = 0;
}

// ---------------- CSR build ----------------
__global__ void k_deg_count(const int* __restrict__ ei) {
    int e = (blockIdx.x * blockDim.x + threadIdx.x) * 4;
    if (e >= N_EDGES) return;
    int4 d = *(const int4*)(ei + N_EDGES + e);
    atomicAdd(&g_deg[d.x], 1);
    atomicAdd(&g_deg[d.y], 1);
    atomicAdd(&g_deg[d.z], 1);
    atomicAdd(&g_deg[d.w], 1);
}
__global__ void __launch_bounds__(SCAN_B) k_scan1() {
    int i = blockIdx.x * SCAN_B + threadIdx.x;
    int lane = threadIdx.x & 31, wid = threadIdx.x >> 5;
    int v = (i < N_NODES) ? g_deg[i] : 0;
#pragma unroll
    for (int o = 16; o > 0; o >>= 1) v += __shfl_down_sync(0xffffffffu, v, o);
    __shared__ int ws[32];
    if (lane == 0) ws[wid] = v;
    __syncthreads();
    if (wid == 0) {
        int t = ws[lane];
#pragma unroll
        for (int o = 16; o > 0; o >>= 1) t += __shfl_down_sync(0xffffffffu, t, o);
        if (lane == 0) g_bsum[blockIdx.x] = t;
    }
}
__global__ void __launch_bounds__(SCAN_B) k_scan3() {
    const int tid = threadIdx.x;
    const int lane = tid & 31, wid = tid >> 5;
    __shared__ int ws[32];
    __shared__ int s_boff;

    int bv = (tid < blockIdx.x && tid < NBLK) ? g_bsum[tid] : 0;
#pragma unroll
    for (int o = 16; o > 0; o >>= 1) bv += __shfl_down_sync(0xffffffffu, bv, o);
    if (lane == 0) ws[wid] = bv;
    __syncthreads();
    if (wid == 0) {
        int t = ws[lane];
#pragma unroll
        for (int o = 16; o > 0; o >>= 1) t += __shfl_down_sync(0xffffffffu, t, o);
        if (lane == 0) s_boff = t;
    }
    __syncthreads();

    int i = blockIdx.x * SCAN_B + tid;
    int d = (i < N_NODES) ? g_deg[i] : 0;
    int v = d;
#pragma unroll
    for (int o = 1; o < 32; o <<= 1) {
        int n = __shfl_up_sync(0xffffffffu, v, o);
        if (lane >= o) v += n;
    }
    __syncthreads();
    if (lane == 31) ws[wid] = v;
    __syncthreads();
    if (wid == 0) {
        int t = ws[lane];
#pragma unroll
        for (int o = 1; o < 32; o <<= 1) {
            int n = __shfl_up_sync(0xffffffffu, t, o);
            if (lane >= o) t += n;
        }
        ws[lane] = t;
    }
    __syncthreads();
    int excl = s_boff + ((wid > 0) ? ws[wid - 1] : 0) + (v - d);
    if (i < N_NODES) {
        g_rowptr[i] = excl;
        g_cursor[i] = excl;
        g_dinv[i]   = rsqrtf((float)d + 1.0f);
    }
}
__global__ void k_csr_scatter(const int* __restrict__ ei) {
    int e = (blockIdx.x * blockDim.x + threadIdx.x) * 4;
    if (e >= N_EDGES) return;
    int4 s = *(const int4*)(ei + e);
    int4 d = *(const int4*)(ei + N_EDGES + e);
    int p0 = atomicAdd(&g_cursor[d.x], 1); g_srcs[p0] = s.x;
    int p1 = atomicAdd(&g_cursor[d.y], 1); g_srcs[p1] = s.y;
    int p2 = atomicAdd(&g_cursor[d.z], 1); g_srcs[p2] = s.z;
    int p3 = atomicAdd(&g_cursor[d.w], 1); g_srcs[p3] = s.w;
}

// ---------------- GEMM1: mma.sync bf16 hi/lo split -------------------------
#define A_OFF(buf, sp) ((size_t)((buf) * 2 + (sp)) * 18432)
#define B_OFF(buf, sp) (73728 + (size_t)((buf) * 2 + (sp)) * 9216)
#define GEMM1_SMEM (73728 + 4 * 9216)   // 110592 B

__device__ __forceinline__ void g1_load_chunk(const float* __restrict__ x,
                                              const __nv_bfloat16* __restrict__ wh,
                                              const __nv_bfloat16* __restrict__ wl,
                                              char* smem, int rowBase, int c, int buf,
                                              int tid) {
    char* ah = smem + A_OFF(buf, 0);
    char* al = smem + A_OFF(buf, 1);
#pragma unroll
    for (int i = 0; i < 8; i++) {
        int idx = tid + i * 256;
        int row = idx >> 4;
        int kq  = (idx & 15) * 4;
        int grow = rowBase + row;
        float4 v = make_float4(0.f, 0.f, 0.f, 0.f);
        if (grow < N_NODES)
            v = *(const float4*)(x + (size_t)grow * N_FEATS + c * 64 + kq);
        __nv_bfloat16 h0 = __float2bfloat16(v.x), h1 = __float2bfloat16(v.y);
        __nv_bfloat16 h2 = __float2bfloat16(v.z), h3 = __float2bfloat16(v.w);
        __nv_bfloat16 l0 = __float2bfloat16(v.x - __bfloat162float(h0));
        __nv_bfloat16 l1 = __float2bfloat16(v.y - __bfloat162float(h1));
        __nv_bfloat16 l2 = __float2bfloat16(v.z - __bfloat162float(h2));
        __nv_bfloat16 l3 = __float2bfloat16(v.w - __bfloat162float(h3));
        __nv_bfloat162 hp0 = __halves2bfloat162(h0, h1), hp1 = __halves2bfloat162(h2, h3);
        __nv_bfloat162 lp0 = __halves2bfloat162(l0, l1), lp1 = __halves2bfloat162(l2, l3);
        uint2 hv = make_uint2(*(uint32_t*)&hp0, *(uint32_t*)&hp1);
        uint2 lv = make_uint2(*(uint32_t*)&lp0, *(uint32_t*)&lp1);
        size_t off = ((size_t)row * 72 + kq) * 2;
        *(uint2*)(ah + off) = hv;
        *(uint2*)(al + off) = lv;
    }
    char* bh = smem + B_OFF(buf, 0);
    char* bl = smem + B_OFF(buf, 1);
#pragma unroll
    for (int i = 0; i < 2; i++) {
        int idx = tid + i * 256;
        int n = idx >> 3, j = idx & 7;
        uint4 vh = *(const uint4*)(wh + (size_t)n * N_FEATS + c * 64 + j * 8);
        uint4 vl = *(const uint4*)(wl + (size_t)n * N_FEATS + c * 64 + j * 8);
        size_t off = ((size_t)n * 72 + j * 8) * 2;
        *(uint4*)(bh + off) = vh;
        *(uint4*)(bl + off) = vl;
    }
}

__global__ void __launch_bounds__(256) k_gemm1_mma(const float* __restrict__ x,
                                                   const __nv_bfloat16* __restrict__ wh,
                                                   const __nv_bfloat16* __restrict__ wl) {
    extern __shared__ __align__(16) char smem[];
    const uint32_t sb = smem_u32(smem);
    const int tid = threadIdx.x, w = tid >> 5, lane = tid & 31;
    const int rowBase = blockIdx.x * 128;

    float acc[8][4];
#pragma unroll
    for (int s = 0; s < 8; s++)
#pragma unroll
        for (int j = 0; j < 4; j++) acc[s][j] = 0.f;

    g1_load_chunk(x, g_w1hi, g_w1lo, smem, rowBase, 0, 0, tid);
    __syncthreads();

    const int arow = w * 16 + (lane & 15);
    const int acolbase = ((lane >> 4) & 1) * 8;
    const int brow = (lane & 7) + ((lane >> 4) & 1) * 8;
    const int bcolbase = ((lane >> 3) & 1) * 8;

    int buf = 0;
    for (int c = 0; c < 8; c++) {
        if (c < 7)
            g1_load_chunk(x, g_w1hi, g_w1lo, smem, rowBase, c + 1, buf ^ 1, tid);

        const uint32_t aH = sb + (uint32_t)A_OFF(buf, 0);
        const uint32_t aL = sb + (uint32_t)A_OFF(buf, 1);
        const uint32_t bH = sb + (uint32_t)B_OFF(buf, 0);
        const uint32_t bL = sb + (uint32_t)B_OFF(buf, 1);

#pragma unroll
        for (int t = 0; t < 4; t++) {
            int kk = t * 16;
            uint32_t ahr[4], alr[4];
            uint32_t aoff = (uint32_t)((arow * 72 + kk + acolbase) * 2);
            ldm_x4(ahr[0], ahr[1], ahr[2], ahr[3], aH + aoff);
            ldm_x4(alr[0], alr[1], alr[2], alr[3], aL + aoff);
#pragma unroll
            for (int p = 0; p < 4; p++) {
                int n0 = p * 16;
                uint32_t boff = (uint32_t)((((n0 + brow) * 72) + kk + bcolbase) * 2);
                uint32_t bh0, bh1, bh2, bh3, bl0, bl1, bl2, bl3;
                ldm_x4(bh0, bh1, bh2, bh3, bH + boff);
                ldm_x4(bl0, bl1, bl2, bl3, bL + boff);
                mma16816(acc[2 * p],     ahr, bh0, bh1);
                mma16816(acc[2 * p],     ahr, bl0, bl1);
                mma16816(acc[2 * p],     alr, bh0, bh1);
                mma16816(acc[2 * p + 1], ahr, bh2, bh3);
                mma16816(acc[2 * p + 1], ahr, bl2, bl3);
                mma16816(acc[2 * p + 1], alr, bh2, bh3);
            }
        }
        __syncthreads();
        buf ^= 1;
    }

    const int r0 = rowBase + w * 16 + (lane >> 2);
    const int cb = (lane & 3) * 2;
#pragma unroll
    for (int s = 0; s < 8; s++) {
        int col = s * 8 + cb;
        if (r0 < N_NODES)
            *(float2*)(g_h1 + (size_t)r0 * HIDDEN + col) = make_float2(acc[s][0], acc[s][1]);
        if (r0 + 8 < N_NODES)
            *(float2*)(g_h1 + (size_t)(r0 + 8) * HIDDEN + col) = make_float2(acc[s][2], acc[s][3]);
    }
}

// ------- FUSED layer-1 aggregation + relu + GEMM2 (64->40 matvec) ----------
// 16 groups x 16 lanes; gather into registers, relu'd h staged in smem,
// lanes 0..9 then compute 4 outputs each against W2^T (staged once per block).
__global__ void __launch_bounds__(256) k_agg1_gemm2(const float* __restrict__ h1,
                                                    const float* __restrict__ b1,
                                                    float* __restrict__ h2) {
    __shared__ float w2s[HIDDEN * N_CLS];   // 10240 B
    __shared__ float sh[16][68];            // relu'd h per group, padded
    const int tid  = threadIdx.x;
    const int g    = tid >> 4;
    const int lane = tid & 15;
    const int n    = blockIdx.x * 16 + g;

    for (int i = tid; i < 640; i += 256)
        ((float4*)w2s)[i] = ((const float4*)g_w2t)[i];
    __syncthreads();

    if (n >= N_NODES) return;

    const float dn = g_dinv[n];
    const int start = g_rowptr[n];
    const int end   = start + g_deg[n];

    float4 v = *(const float4*)(h1 + (size_t)n * HIDDEN + lane * 4);
    float s = dn * dn;
    float4 acc = make_float4(v.x * s, v.y * s, v.z * s, v.w * s);

    int e = start;
    for (; e + 4 <= end; e += 4) {
        int s0 = g_srcs[e], s1 = g_srcs[e + 1], s2 = g_srcs[e + 2], s3 = g_srcs[e + 3];
        float w0 = g_dinv[s0] * dn, w1 = g_dinv[s1] * dn;
        float w2 = g_dinv[s2] * dn, w3 = g_dinv[s3] * dn;
        float4 m0 = *(const float4*)(h1 + (size_t)s0 * HIDDEN + lane * 4);
        float4 m1 = *(const float4*)(h1 + (size_t)s1 * HIDDEN + lane * 4);
        float4 m2 = *(const float4*)(h1 + (size_t)s2 * HIDDEN + lane * 4);
        float4 m3 = *(const float4*)(h1 + (size_t)s3 * HIDDEN + lane * 4);
        acc.x += m0.x * w0 + m1.x * w1 + m2.x * w2 + m3.x * w3;
        acc.y += m0.y * w0 + m1.y * w1 + m2.y * w2 + m3.y * w3;
        acc.z += m0.z * w0 + m1.z * w1 + m2.z * w2 + m3.z * w3;
        acc.w += m0.w * w0 + m1.w * w1 + m2.w * w2 + m3.w * w3;
    }
    for (; e < end; e++) {
        int src = g_srcs[e];
        float w = g_dinv[src] * dn;
        float4 m = *(const float4*)(h1 + (size_t)src * HIDDEN + lane * 4);
        acc.x += m.x * w; acc.y += m.y * w; acc.z += m.z * w; acc.w += m.w * w;
    }
    float4 bb = *(const float4*)(b1 + lane * 4);
    sh[g][lane * 4 + 0] = fmaxf(acc.x + bb.x, 0.f);
    sh[g][lane * 4 + 1] = fmaxf(acc.y + bb.y, 0.f);
    sh[g][lane * 4 + 2] = fmaxf(acc.z + bb.z, 0.f);
    sh[g][lane * 4 + 3] = fmaxf(acc.w + bb.w, 0.f);
    __syncwarp();

    if (lane < 10) {
        float4 o = make_float4(0.f, 0.f, 0.f, 0.f);
        const float* hrow = sh[g];
#pragma unroll 8
        for (int k = 0; k < HIDDEN; k++) {
            float hv = hrow[k];
            float4 wv = *(const float4*)&w2s[k * N_CLS + lane * 4];
            o.x += hv * wv.x; o.y += hv * wv.y; o.z += hv * wv.z; o.w += hv * wv.w;
        }
        *(float4*)(h2 + (size_t)n * N_CLS + lane * 4) = o;
    }
}

// ---------------- layer-2 aggregation ----------------
__global__ void __launch_bounds__(256) k_agg2_gather(const float* __restrict__ h2,
                                                     const float* __restrict__ b2,
                                                     float* __restrict__ out) {
    const int tid  = threadIdx.x;
    const int g    = tid >> 4;
    const int lane = tid & 15;
    const int n    = blockIdx.x * 16 + g;
    if (n >= N_NODES || lane >= 10) return;

    const float dn = g_dinv[n];
    const int start = g_rowptr[n];
    const int end   = start + g_deg[n];

    float4 v = *(const float4*)(h2 + (size_t)n * N_CLS + lane * 4);
    float s = dn * dn;
    float4 acc = make_float4(v.x * s, v.y * s, v.z * s, v.w * s);

    int e = start;
    for (; e + 4 <= end; e += 4) {
        int s0 = g_srcs[e], s1 = g_srcs[e + 1], s2 = g_srcs[e + 2], s3 = g_srcs[e + 3];
        float w0 = g_dinv[s0] * dn, w1 = g_dinv[s1] * dn;
        float w2 = g_dinv[s2] * dn, w3 = g_dinv[s3] * dn;
        float4 m0 = *(const float4*)(h2 + (size_t)s0 * N_CLS + lane * 4);
        float4 m1 = *(const float4*)(h2 + (size_t)s1 * N_CLS + lane * 4);
        float4 m2 = *(const float4*)(h2 + (size_t)s2 * N_CLS + lane * 4);
        float4 m3 = *(const float4*)(h2 + (size_t)s3 * N_CLS + lane * 4);
        acc.x += m0.x * w0 + m1.x * w1 + m2.x * w2 + m3.x * w3;
        acc.y += m0.y * w0 + m1.y * w1 + m2.y * w2 + m3.y * w3;
        acc.z += m0.z * w0 + m1.z * w1 + m2.z * w2 + m3.z * w3;
        acc.w += m0.w * w0 + m1.w * w1 + m2.w * w2 + m3.w * w3;
    }
    for (; e < end; e++) {
        int src = g_srcs[e];
        float w = g_dinv[src] * dn;
        float4 m = *(const float4*)(h2 + (size_t)src * N_CLS + lane * 4);
        acc.x += m.x * w; acc.y += m.y * w; acc.z += m.z * w; acc.w += m.w * w;
    }
    float4 bb = *(const float4*)(b2 + lane * 4);
    acc.x += bb.x; acc.y += bb.y; acc.z += bb.z; acc.w += bb.w;
    *(float4*)(out + (size_t)n * N_CLS + lane * 4) = acc;
}

// ---------------- launch (single stream, R6 ordering) ----------------
extern "C" void kernel_launch(void* const* d_in, const int* in_sizes, int n_in,
                              void* d_out, int out_size) {
    const float* x  = (const float*)d_in[0];
    const int*   ei = (const int*)d_in[1];
    const float* W1 = (const float*)d_in[2];
    const float* b1 = (const float*)d_in[3];
    const float* W2 = (const float*)d_in[4];
    const float* b2 = (const float*)d_in[5];
    float* out = (float*)d_out;

    float *h1, *h2;
    __nv_bfloat16 *wh, *wl;
    cudaGetSymbolAddress((void**)&h1, g_h1);
    cudaGetSymbolAddress((void**)&h2, g_h2);
    cudaGetSymbolAddress((void**)&wh, g_w1hi);
    cudaGetSymbolAddress((void**)&wl, g_w1lo);

    k_prep<<<(N_NODES + 255) / 256, 256>>>(W1, W2);

    k_deg_count<<<(N_EDGES / 4 + 255) / 256, 256>>>(ei);
    k_scan1<<<NBLK, SCAN_B>>>();
    k_scan3<<<NBLK, SCAN_B>>>();
    k_csr_scatter<<<(N_EDGES / 4 + 255) / 256, 256>>>(ei);

    cudaFuncSetAttribute(k_gemm1_mma, cudaFuncAttributeMaxDynamicSharedMemorySize,
                         GEMM1_SMEM);
    k_gemm1_mma<<<(N_NODES + 127) / 128, 256, GEMM1_SMEM>>>(x, wh, wl);

    // fused: aggregate layer1 + relu + bias + (64->40 matvec) -> h2
    k_agg1_gemm2<<<(N_NODES + 15) / 16, 256>>>(h1, b1, h2);

    // layer-2 aggregation -> out
    k_agg2_gather<<<(N_NODES + 15) / 16, 256>>>(h2, b2, out);
}

// round 9
// speedup vs baseline: 1.1828x; 1.1828x over previous
#include <cuda_runtime.h>
#include <cuda_bf16.h>
#include <cstdint>

#define N_NODES 100000
#define N_FEATS 512
#define HIDDEN  64
#define N_CLS   40
#define N_EDGES 1600000
#define SCAN_B  1024
#define NBLK    ((N_NODES + SCAN_B - 1) / SCAN_B)   // 98

// ---------------- scratch ----------------
__device__ float g_dinv[N_NODES];
__device__ float g_h1[(size_t)N_NODES * HIDDEN];   // gemm1 out; reused as h2 [N][40]
__device__ float g_out1[(size_t)N_NODES * HIDDEN];
__device__ float g_w2t[HIDDEN * N_CLS];            // [64][40]
__device__ __nv_bfloat16 g_w1hi[HIDDEN * N_FEATS];
__device__ __nv_bfloat16 g_w1lo[HIDDEN * N_FEATS];
__device__ int   g_deg[N_NODES];
__device__ int   g_rowptr[N_NODES];
__device__ int   g_cursor[N_NODES];
__device__ int   g_srcs[N_EDGES];
__device__ int   g_bsum[NBLK];

// ---------------- helpers ----------------
__device__ __forceinline__ uint32_t smem_u32(const void* p) {
    uint32_t a;
    asm("{ .reg .u64 t; cvta.to.shared.u64 t, %1; cvt.u32.u64 %0, t; }" : "=r"(a) : "l"(p));
    return a;
}
__device__ __forceinline__ void ldm_x4(uint32_t& r0, uint32_t& r1, uint32_t& r2,
                                       uint32_t& r3, uint32_t addr) {
    asm volatile("ldmatrix.sync.aligned.m8n8.x4.shared.b16 {%0,%1,%2,%3}, [%4];"
                 : "=r"(r0), "=r"(r1), "=r"(r2), "=r"(r3) : "r"(addr));
}
__device__ __forceinline__ void mma16816(float* d, const uint32_t* a,
                                         uint32_t b0, uint32_t b1) {
    asm volatile(
        "mma.sync.aligned.m16n8k16.row.col.f32.bf16.bf16.f32 "
        "{%0,%1,%2,%3}, {%4,%5,%6,%7}, {%8,%9}, {%0,%1,%2,%3};"
        : "+f"(d[0]), "+f"(d[1]), "+f"(d[2]), "+f"(d[3])
        : "r"(a[0]), "r"(a[1]), "r"(a[2]), "r"(a[3]), "r"(b0), "r"(b1));
}
__device__ __forceinline__ void cp16(uint32_t dst, const void* src) {
    asm volatile("cp.async.cg.shared.global [%0], [%1], 16;" :: "r"(dst), "l"(src));
}

// ---------------- fused prep ----------------
__global__ void k_prep(const float* __restrict__ W1, const float* __restrict__ W2) {
    int i = blockIdx.x * blockDim.x + threadIdx.x;
    if (i < HIDDEN * N_FEATS) {
        float v = W1[i];
        __nv_bfloat16 h = __float2bfloat16(v);
        g_w1hi[i] = h;
        g_w1lo[i] = __float2bfloat16(v - __bfloat162float(h));
    }
    if (i < HIDDEN * N_CLS) {
        int k = i / N_CLS, j = i - k * N_CLS;
        g_w2t[i] = W2[j * HIDDEN + k];
    }
    if (i < N_NODES) g_deg[i] = 0;
}

// ---------------- CSR build ----------------
__global__ void k_deg_count(const int* __restrict__ ei) {
    int e = (blockIdx.x * blockDim.x + threadIdx.x) * 4;
    if (e >= N_EDGES) return;
    int4 d = *(const int4*)(ei + N_EDGES + e);
    atomicAdd(&g_deg[d.x], 1);
    atomicAdd(&g_deg[d.y], 1);
    atomicAdd(&g_deg[d.z], 1);
    atomicAdd(&g_deg[d.w], 1);
}
__global__ void __launch_bounds__(SCAN_B) k_scan1() {
    int i = blockIdx.x * SCAN_B + threadIdx.x;
    int lane = threadIdx.x & 31, wid = threadIdx.x >> 5;
    int v = (i < N_NODES) ? g_deg[i] : 0;
#pragma unroll
    for (int o = 16; o > 0; o >>= 1) v += __shfl_down_sync(0xffffffffu, v, o);
    __shared__ int ws[32];
    if (lane == 0) ws[wid] = v;
    __syncthreads();
    if (wid == 0) {
        int t = ws[lane];
#pragma unroll
        for (int o = 16; o > 0; o >>= 1) t += __shfl_down_sync(0xffffffffu, t, o);
        if (lane == 0) g_bsum[blockIdx.x] = t;
    }
}
__global__ void __launch_bounds__(SCAN_B) k_scan3() {
    const int tid = threadIdx.x;
    const int lane = tid & 31, wid = tid >> 5;
    __shared__ int ws[32];
    __shared__ int s_boff;

    int bv = (tid < blockIdx.x && tid < NBLK) ? g_bsum[tid] : 0;
#pragma unroll
    for (int o = 16; o > 0; o >>= 1) bv += __shfl_down_sync(0xffffffffu, bv, o);
    if (lane == 0) ws[wid] = bv;
    __syncthreads();
    if (wid == 0) {
        int t = ws[lane];
#pragma unroll
        for (int o = 16; o > 0; o >>= 1) t += __shfl_down_sync(0xffffffffu, t, o);
        if (lane == 0) s_boff = t;
    }
    __syncthreads();

    int i = blockIdx.x * SCAN_B + tid;
    int d = (i < N_NODES) ? g_deg[i] : 0;
    int v = d;
#pragma unroll
    for (int o = 1; o < 32; o <<= 1) {
        int n = __shfl_up_sync(0xffffffffu, v, o);
        if (lane >= o) v += n;
    }
    __syncthreads();
    if (lane == 31) ws[wid] = v;
    __syncthreads();
    if (wid == 0) {
        int t = ws[lane];
#pragma unroll
        for (int o = 1; o < 32; o <<= 1) {
            int n = __shfl_up_sync(0xffffffffu, t, o);
            if (lane >= o) t += n;
        }
        ws[lane] = t;
    }
    __syncthreads();
    int excl = s_boff + ((wid > 0) ? ws[wid - 1] : 0) + (v - d);
    if (i < N_NODES) {
        g_rowptr[i] = excl;
        g_cursor[i] = excl;
        g_dinv[i]   = rsqrtf((float)d + 1.0f);
    }
}
__global__ void k_csr_scatter(const int* __restrict__ ei) {
    int e = (blockIdx.x * blockDim.x + threadIdx.x) * 4;
    if (e >= N_EDGES) return;
    int4 s = *(const int4*)(ei + e);
    int4 d = *(const int4*)(ei + N_EDGES + e);
    int p0 = atomicAdd(&g_cursor[d.x], 1); g_srcs[p0] = s.x;
    int p1 = atomicAdd(&g_cursor[d.y], 1); g_srcs[p1] = s.y;
    int p2 = atomicAdd(&g_cursor[d.z], 1); g_srcs[p2] = s.z;
    int p3 = atomicAdd(&g_cursor[d.w], 1); g_srcs[p3] = s.w;
}

// ---------------- GEMM1: mma.sync bf16 hi/lo split, pipelined staging -------
#define A_OFF(buf, sp) ((size_t)((buf) * 2 + (sp)) * 18432)
#define B_OFF(buf, sp) (73728 + (size_t)((buf) * 2 + (sp)) * 9216)
#define GEMM1_SMEM (73728 + 4 * 9216)   // 110592 B

// convert 8 float4 of X (already in regs) into hi/lo bf16 tiles in smem
__device__ __forceinline__ void g1_cvt_store(const float4* xr, char* smem, int buf,
                                             int tid) {
    char* ah = smem + A_OFF(buf, 0);
    char* al = smem + A_OFF(buf, 1);
#pragma unroll
    for (int i = 0; i < 8; i++) {
        int idx = tid + i * 256;
        int row = idx >> 4;
        int kq  = (idx & 15) * 4;
        float4 v = xr[i];
        __nv_bfloat16 h0 = __float2bfloat16(v.x), h1 = __float2bfloat16(v.y);
        __nv_bfloat16 h2 = __float2bfloat16(v.z), h3 = __float2bfloat16(v.w);
        __nv_bfloat16 l0 = __float2bfloat16(v.x - __bfloat162float(h0));
        __nv_bfloat16 l1 = __float2bfloat16(v.y - __bfloat162float(h1));
        __nv_bfloat16 l2 = __float2bfloat16(v.z - __bfloat162float(h2));
        __nv_bfloat16 l3 = __float2bfloat16(v.w - __bfloat162float(h3));
        __nv_bfloat162 hp0 = __halves2bfloat162(h0, h1), hp1 = __halves2bfloat162(h2, h3);
        __nv_bfloat162 lp0 = __halves2bfloat162(l0, l1), lp1 = __halves2bfloat162(l2, l3);
        uint2 hv = make_uint2(*(uint32_t*)&hp0, *(uint32_t*)&hp1);
        uint2 lv = make_uint2(*(uint32_t*)&lp0, *(uint32_t*)&lp1);
        size_t off = ((size_t)row * 72 + kq) * 2;
        *(uint2*)(ah + off) = hv;
        *(uint2*)(al + off) = lv;
    }
}

__device__ __forceinline__ void g1_ldg_x(const float* __restrict__ x, float4* xr,
                                         int rowBase, int c, int tid) {
#pragma unroll
    for (int i = 0; i < 8; i++) {
        int idx = tid + i * 256;
        int row = idx >> 4;
        int kq  = (idx & 15) * 4;
        int grow = rowBase + row;
        xr[i] = make_float4(0.f, 0.f, 0.f, 0.f);
        if (grow < N_NODES)
            xr[i] = *(const float4*)(x + (size_t)grow * N_FEATS + c * 64 + kq);
    }
}

__device__ __forceinline__ void g1_cpasync_w(const __nv_bfloat16* __restrict__ wh,
                                             const __nv_bfloat16* __restrict__ wl,
                                             uint32_t sb, int c, int buf, int tid) {
#pragma unroll
    for (int i = 0; i < 2; i++) {
        int idx = tid + i * 256;
        int n = idx >> 3, j = idx & 7;
        uint32_t off = (uint32_t)(((size_t)n * 72 + j * 8) * 2);
        cp16(sb + (uint32_t)B_OFF(buf, 0) + off, wh + (size_t)n * N_FEATS + c * 64 + j * 8);
        cp16(sb + (uint32_t)B_OFF(buf, 1) + off, wl + (size_t)n * N_FEATS + c * 64 + j * 8);
    }
    asm volatile("cp.async.commit_group;" ::: "memory");
}

__global__ void __launch_bounds__(256) k_gemm1_mma(const float* __restrict__ x,
                                                   const __nv_bfloat16* __restrict__ wh,
                                                   const __nv_bfloat16* __restrict__ wl) {
    extern __shared__ __align__(16) char smem[];
    const uint32_t sb = smem_u32(smem);
    const int tid = threadIdx.x, w = tid >> 5, lane = tid & 31;
    const int rowBase = blockIdx.x * 128;

    float acc[8][4];
#pragma unroll
    for (int s = 0; s < 8; s++)
#pragma unroll
        for (int j = 0; j < 4; j++) acc[s][j] = 0.f;

    // prologue: stage chunk 0
    {
        float4 xr[8];
        g1_ldg_x(x, xr, rowBase, 0, tid);
        g1_cpasync_w(wh, wl, sb, 0, 0, tid);
        g1_cvt_store(xr, smem, 0, tid);
        asm volatile("cp.async.wait_group 0;" ::: "memory");
    }
    __syncthreads();

    const int arow = w * 16 + (lane & 15);
    const int acolbase = ((lane >> 4) & 1) * 8;
    const int brow = (lane & 7) + ((lane >> 4) & 1) * 8;
    const int bcolbase = ((lane >> 3) & 1) * 8;

    int buf = 0;
    for (int c = 0; c < 8; c++) {
        float4 xr[8];
        if (c < 7) {
            g1_ldg_x(x, xr, rowBase, c + 1, tid);     // in-flight under MMA
            g1_cpasync_w(wh, wl, sb, c + 1, buf ^ 1, tid);
        }

        const uint32_t aH = sb + (uint32_t)A_OFF(buf, 0);
        const uint32_t aL = sb + (uint32_t)A_OFF(buf, 1);
        const uint32_t bH = sb + (uint32_t)B_OFF(buf, 0);
        const uint32_t bL = sb + (uint32_t)B_OFF(buf, 1);

#pragma unroll
        for (int t = 0; t < 4; t++) {
            int kk = t * 16;
            uint32_t ahr[4], alr[4];
            uint32_t aoff = (uint32_t)((arow * 72 + kk + acolbase) * 2);
            ldm_x4(ahr[0], ahr[1], ahr[2], ahr[3], aH + aoff);
            ldm_x4(alr[0], alr[1], alr[2], alr[3], aL + aoff);
#pragma unroll
            for (int p = 0; p < 4; p++) {
                int n0 = p * 16;
                uint32_t boff = (uint32_t)((((n0 + brow) * 72) + kk + bcolbase) * 2);
                uint32_t bh0, bh1, bh2, bh3, bl0, bl1, bl2, bl3;
                ldm_x4(bh0, bh1, bh2, bh3, bH + boff);
                ldm_x4(bl0, bl1, bl2, bl3, bL + boff);
                mma16816(acc[2 * p],     ahr, bh0, bh1);
                mma16816(acc[2 * p],     ahr, bl0, bl1);
                mma16816(acc[2 * p],     alr, bh0, bh1);
                mma16816(acc[2 * p + 1], ahr, bh2, bh3);
                mma16816(acc[2 * p + 1], ahr, bl2, bl3);
                mma16816(acc[2 * p + 1], alr, bh2, bh3);
            }
        }

        if (c < 7) {
            g1_cvt_store(xr, smem, buf ^ 1, tid);     // loads have landed by now
            asm volatile("cp.async.wait_group 0;" ::: "memory");
        }
        __syncthreads();
        buf ^= 1;
    }

    const int r0 = rowBase + w * 16 + (lane >> 2);
    const int cb = (lane & 3) * 2;
#pragma unroll
    for (int s = 0; s < 8; s++) {
        int col = s * 8 + cb;
        if (r0 < N_NODES)
            *(float2*)(g_h1 + (size_t)r0 * HIDDEN + col) = make_float2(acc[s][0], acc[s][1]);
        if (r0 + 8 < N_NODES)
            *(float2*)(g_h1 + (size_t)(r0 + 8) * HIDDEN + col) = make_float2(acc[s][2], acc[s][3]);
    }
}

// ---------------- layer-1 aggregation (R6 version) ----------------
__global__ void __launch_bounds__(256) k_agg1_gather(const float* __restrict__ h1,
                                                     const float* __restrict__ b1,
                                                     float* __restrict__ out1) {
    const int tid  = threadIdx.x;
    const int g    = tid >> 4;
    const int lane = tid & 15;
    const int n    = blockIdx.x * 16 + g;
    if (n >= N_NODES) return;

    const float dn = g_dinv[n];
    const int start = g_rowptr[n];
    const int end   = start + g_deg[n];

    float4 v = *(const float4*)(h1 + (size_t)n * HIDDEN + lane * 4);
    float s = dn * dn;
    float4 acc = make_float4(v.x * s, v.y * s, v.z * s, v.w * s);

    int e = start;
    for (; e + 4 <= end; e += 4) {
        int s0 = g_srcs[e], s1 = g_srcs[e + 1], s2 = g_srcs[e + 2], s3 = g_srcs[e + 3];
        float w0 = g_dinv[s0] * dn, w1 = g_dinv[s1] * dn;
        float w2 = g_dinv[s2] * dn, w3 = g_dinv[s3] * dn;
        float4 m0 = *(const float4*)(h1 + (size_t)s0 * HIDDEN + lane * 4);
        float4 m1 = *(const float4*)(h1 + (size_t)s1 * HIDDEN + lane * 4);
        float4 m2 = *(const float4*)(h1 + (size_t)s2 * HIDDEN + lane * 4);
        float4 m3 = *(const float4*)(h1 + (size_t)s3 * HIDDEN + lane * 4);
        acc.x += m0.x * w0 + m1.x * w1 + m2.x * w2 + m3.x * w3;
        acc.y += m0.y * w0 + m1.y * w1 + m2.y * w2 + m3.y * w3;
        acc.z += m0.z * w0 + m1.z * w1 + m2.z * w2 + m3.z * w3;
        acc.w += m0.w * w0 + m1.w * w1 + m2.w * w2 + m3.w * w3;
    }
    for (; e < end; e++) {
        int src = g_srcs[e];
        float w = g_dinv[src] * dn;
        float4 m = *(const float4*)(h1 + (size_t)src * HIDDEN + lane * 4);
        acc.x += m.x * w; acc.y += m.y * w; acc.z += m.z * w; acc.w += m.w * w;
    }
    float4 bb = *(const float4*)(b1 + lane * 4);
    acc.x = fmaxf(acc.x + bb.x, 0.f);
    acc.y = fmaxf(acc.y + bb.y, 0.f);
    acc.z = fmaxf(acc.z + bb.z, 0.f);
    acc.w = fmaxf(acc.w + bb.w, 0.f);
    *(float4*)(out1 + (size_t)n * HIDDEN + lane * 4) = acc;
}

// ---------------- GEMM2 (R6 version) ----------------
__global__ void __launch_bounds__(256) k_gemm2(const float* __restrict__ h1r,
                                               float* __restrict__ h2) {
    __shared__ float xs[128][65];
    __shared__ float wsT[HIDDEN * N_CLS];
    const int tid = threadIdx.x;
    const int r = tid & 127;
    const int q = tid >> 7;
    const int rowBase = blockIdx.x * 128;

#pragma unroll
    for (int m = 0; m < 8; m++) {
        int idx4 = tid + m * 256;
        int row = idx4 >> 4, kq = (idx4 & 15) * 4;
        int grow = rowBase + row;
        float4 v = make_float4(0.f, 0.f, 0.f, 0.f);
        if (grow < N_NODES)
            v = *(const float4*)(h1r + (size_t)grow * HIDDEN + kq);
        xs[row][kq + 0] = v.x; xs[row][kq + 1] = v.y;
        xs[row][kq + 2] = v.z; xs[row][kq + 3] = v.w;
    }
    for (int idx4 = tid; idx4 < 640; idx4 += 256)
        ((float4*)wsT)[idx4] = ((const float4*)g_w2t)[idx4];
    __syncthreads();

    unsigned long long acc[10];
#pragma unroll
    for (int i = 0; i < 10; i++) acc[i] = 0ull;

#pragma unroll 4
    for (int k = 0; k < HIDDEN; k++) {
        float xv = xs[r][k];
        unsigned long long xx;
        asm("mov.b64 %0, {%1, %1};" : "=l"(xx) : "f"(xv));
        const unsigned long long* wrow =
            (const unsigned long long*)(wsT + k * N_CLS + q * 20);
#pragma unroll
        for (int c = 0; c < 10; c++) {
            unsigned long long w2 = wrow[c];
            asm("fma.rn.f32x2 %0, %1, %2, %0;" : "+l"(acc[c]) : "l"(w2), "l"(xx));
        }
    }

    int grow = rowBase + r;
    if (grow < N_NODES) {
        float* dst = h2 + (size_t)grow * N_CLS + q * 20;
#pragma unroll
        for (int c = 0; c < 10; c++) {
            float a0, a1;
            asm("mov.b64 {%0,%1}, %2;" : "=f"(a0), "=f"(a1) : "l"(acc[c]));
            *(float2*)(dst + c * 2) = make_float2(a0, a1);
        }
    }
}

// ---------------- layer-2 aggregation (R6 version) ----------------
__global__ void __launch_bounds__(256) k_agg2_gather(const float* __restrict__ h2,
                                                     const float* __restrict__ b2,
                                                     float* __restrict__ out) {
    const int tid  = threadIdx.x;
    const int g    = tid >> 4;
    const int lane = tid & 15;
    const int n    = blockIdx.x * 16 + g;
    if (n >= N_NODES || lane >= 10) return;

    const float dn = g_dinv[n];
    const int start = g_rowptr[n];
    const int end   = start + g_deg[n];

    float4 v = *(const float4*)(h2 + (size_t)n * N_CLS + lane * 4);
    float s = dn * dn;
    float4 acc = make_float4(v.x * s, v.y * s, v.z * s, v.w * s);

    int e = start;
    for (; e + 4 <= end; e += 4) {
        int s0 = g_srcs[e], s1 = g_srcs[e + 1], s2 = g_srcs[e + 2], s3 = g_srcs[e + 3];
        float w0 = g_dinv[s0] * dn, w1 = g_dinv[s1] * dn;
        float w2 = g_dinv[s2] * dn, w3 = g_dinv[s3] * dn;
        float4 m0 = *(const float4*)(h2 + (size_t)s0 * N_CLS + lane * 4);
        float4 m1 = *(const float4*)(h2 + (size_t)s1 * N_CLS + lane * 4);
        float4 m2 = *(const float4*)(h2 + (size_t)s2 * N_CLS + lane * 4);
        float4 m3 = *(const float4*)(h2 + (size_t)s3 * N_CLS + lane * 4);
        acc.x += m0.x * w0 + m1.x * w1 + m2.x * w2 + m3.x * w3;
        acc.y += m0.y * w0 + m1.y * w1 + m2.y * w2 + m3.y * w3;
        acc.z += m0.z * w0 + m1.z * w1 + m2.z * w2 + m3.z * w3;
        acc.w += m0.w * w0 + m1.w * w1 + m2.w * w2 + m3.w * w3;
    }
    for (; e < end; e++) {
        int src = g_srcs[e];
        float w = g_dinv[src] * dn;
        float4 m = *(const float4*)(h2 + (size_t)src * N_CLS + lane * 4);
        acc.x += m.x * w; acc.y += m.y * w; acc.z += m.z * w; acc.w += m.w * w;
    }
    float4 bb = *(const float4*)(b2 + lane * 4);
    acc.x += bb.x; acc.y += bb.y; acc.z += bb.z; acc.w += bb.w;
    *(float4*)(out + (size_t)n * N_CLS + lane * 4) = acc;
}

// ---------------- launch (single stream, R6 ordering) ----------------
extern "C" void kernel_launch(void* const* d_in, const int* in_sizes, int n_in,
                              void* d_out, int out_size) {
    const float* x  = (const float*)d_in[0];
    const int*   ei = (const int*)d_in[1];
    const float* W1 = (const float*)d_in[2];
    const float* b1 = (const float*)d_in[3];
    const float* W2 = (const float*)d_in[4];
    const float* b2 = (const float*)d_in[5];
    float* out = (float*)d_out;

    float *h1, *out1;
    __nv_bfloat16 *wh, *wl;
    cudaGetSymbolAddress((void**)&h1,   g_h1);
    cudaGetSymbolAddress((void**)&out1, g_out1);
    cudaGetSymbolAddress((void**)&wh,   g_w1hi);
    cudaGetSymbolAddress((void**)&wl,   g_w1lo);

    k_prep<<<(N_NODES + 255) / 256, 256>>>(W1, W2);

    k_deg_count<<<(N_EDGES / 4 + 255) / 256, 256>>>(ei);
    k_scan1<<<NBLK, SCAN_B>>>();
    k_scan3<<<NBLK, SCAN_B>>>();
    k_csr_scatter<<<(N_EDGES / 4 + 255) / 256, 256>>>(ei);

    cudaFuncSetAttribute(k_gemm1_mma, cudaFuncAttributeMaxDynamicSharedMemorySize,
                         GEMM1_SMEM);
    k_gemm1_mma<<<(N_NODES + 127) / 128, 256, GEMM1_SMEM>>>(x, wh, wl);
    k_agg1_gather<<<(N_NODES + 15) / 16, 256>>>(h1, b1, out1);

    k_gemm2<<<(N_NODES + 127) / 128, 256>>>(out1, h1);
    k_agg2_gather<<<(N_NODES + 15) / 16, 256>>>(h1, b2, out);
}